// round 14
// baseline (speedup 1.0000x reference)
#include <cuda_runtime.h>
#include <cuda_fp16.h>
#include <math.h>

#define NN 50000
#define NE 800000
#define NET (NE + NN)       // edges + self loops = 850000
#define HC 256              // H*C
#define NH 4
#define CC 64
#define NB_SCAN 196         // ceil(NN/256)
#define NCHUNK 4
#define CROWS 12544         // 98 * 128, divisible by 8 and 128

// ---------------- scratch (static device globals; no allocs) ----------------
__device__ __align__(16) __half g_h[NN * HC];     // layer-0 transformed features (fp16)
__device__ __align__(16) __half g_h2[NN * HC];    // layer-1 transformed features (fp16)
__device__ __align__(16) __half g_x1[NN * HC];    // layer-0 activated output (fp16)
__device__ __align__(16) float g_acc[NN * HC];    // layer-1 aggregation output (fp32)
__device__ __align__(16) float g_asrc[NN * NH];   // layer-0 alpha
__device__ __align__(16) float g_adst[NN * NH];
__device__ __align__(16) float g_as1[NN * NH];    // layer-1 alpha
__device__ __align__(16) float g_ad1[NN * NH];
__device__ int g_deg[NN];
__device__ int g_off[NN + 1];
__device__ int g_cur[NN];
__device__ int g_part[NB_SCAN];
__device__ int g_adj[NET];                        // src ids grouped by dst
__device__ int g_is64;

// ---------------- zero deg (=1: self-loop pre-counted) + detect dtype ----------------
__global__ void zerodetect_k(const int* ei32) {
    int i = blockIdx.x * blockDim.x + threadIdx.x;
    if (i < NN) g_deg[i] = 1;
    if (i == 0) {
        int ok = 1;
        #pragma unroll
        for (int k = 0; k < 64; k++)
            if (ei32[2 * k + 1] != 0) ok = 0;
        g_is64 = ok;
    }
}

// ---------------- CSR build (real edges only; self-loops planted by scan3) ----------------
__global__ void hist_k(const void* __restrict__ ei) {
    int q = blockIdx.x * blockDim.x + threadIdx.x;
    int e = q * 4;
    if (e >= NE) return;
    int d0, d1, d2, d3;
    if (g_is64) {
        const longlong2* p = (const longlong2*)((const long long*)ei + NE);
        longlong2 a = p[q * 2];
        longlong2 b = p[q * 2 + 1];
        d0 = (int)a.x; d1 = (int)a.y; d2 = (int)b.x; d3 = (int)b.y;
    } else {
        int4 a = ((const int4*)((const int*)ei + NE))[q];
        d0 = a.x; d1 = a.y; d2 = a.z; d3 = a.w;
    }
    atomicAdd(&g_deg[d0], 1);
    atomicAdd(&g_deg[d1], 1);
    atomicAdd(&g_deg[d2], 1);
    atomicAdd(&g_deg[d3], 1);
}

__global__ void scan1_k() {
    __shared__ int sh[256];
    int i = blockIdx.x * 256 + threadIdx.x;
    int v = (i < NN) ? g_deg[i] : 0;
    sh[threadIdx.x] = v; __syncthreads();
    for (int o = 128; o; o >>= 1) {
        if (threadIdx.x < o) sh[threadIdx.x] += sh[threadIdx.x + o];
        __syncthreads();
    }
    if (threadIdx.x == 0) g_part[blockIdx.x] = sh[0];
}

__global__ void scan2_k() {
    __shared__ int sh[256];
    int t = threadIdx.x;
    int v = (t < NB_SCAN) ? g_part[t] : 0;
    sh[t] = v; __syncthreads();
    for (int o = 1; o < 256; o <<= 1) {
        int x = (t >= o) ? sh[t - o] : 0;
        __syncthreads();
        sh[t] += x;
        __syncthreads();
    }
    if (t < NB_SCAN) g_part[t] = sh[t] - v;
}

__global__ void scan3_k() {
    __shared__ int sh[256];
    int t = threadIdx.x;
    int i = blockIdx.x * 256 + t;
    int v = (i < NN) ? g_deg[i] : 0;
    sh[t] = v; __syncthreads();
    for (int o = 1; o < 256; o <<= 1) {
        int x = (t >= o) ? sh[t - o] : 0;
        __syncthreads();
        sh[t] += x;
        __syncthreads();
    }
    if (i < NN) {
        int off = g_part[blockIdx.x] + sh[t] - v;
        g_off[i] = off;
        g_adj[off] = i;
        g_cur[i] = off + 1;
        if (i == NN - 1) g_off[NN] = off + v;
    }
}

__global__ void fill_k(const void* __restrict__ ei) {
    int q = blockIdx.x * blockDim.x + threadIdx.x;
    int e = q * 2;
    if (e >= NE) return;
    int s0, s1, d0, d1;
    if (g_is64) {
        const long long* p = (const long long*)ei;
        longlong2 sv = ((const longlong2*)p)[q];
        longlong2 dv = ((const longlong2*)(p + NE))[q];
        s0 = (int)sv.x; s1 = (int)sv.y;
        d0 = (int)dv.x; d1 = (int)dv.y;
    } else {
        const int* p = (const int*)ei;
        int2 sv = ((const int2*)p)[q];
        int2 dv = ((const int2*)(p + NE))[q];
        s0 = sv.x; s1 = sv.y;
        d0 = dv.x; d1 = dv.y;
    }
    int p0 = atomicAdd(&g_cur[d0], 1);
    g_adj[p0] = s0;
    int p1 = atomicAdd(&g_cur[d1], 1);
    g_adj[p1] = s1;
}

// ---------------- tensor-core GEMM (fp16 HMMA, fp32 accum) ----------------
// ALPHA: fp16 output + per-row alpha dots into pAS/pAD (head = blockIdx.x).
// FMAX:  A-element = max(A, A2 + ab); fp32 output with +bias (final projection).
// AHALF: A operand is fp16 in global memory.
#define APAD 40
#define BPAD 72
__device__ __forceinline__ unsigned su32(const void* p) {
    return (unsigned)__cvta_generic_to_shared(p);
}
__device__ __forceinline__ void ldm_x4(unsigned addr, unsigned& r0, unsigned& r1,
                                       unsigned& r2, unsigned& r3) {
    asm volatile("ldmatrix.sync.aligned.m8n8.x4.shared.b16 {%0,%1,%2,%3},[%4];"
                 : "=r"(r0), "=r"(r1), "=r"(r2), "=r"(r3) : "r"(addr));
}
__device__ __forceinline__ void ldm_x4t(unsigned addr, unsigned& r0, unsigned& r1,
                                        unsigned& r2, unsigned& r3) {
    asm volatile("ldmatrix.sync.aligned.m8n8.x4.trans.shared.b16 {%0,%1,%2,%3},[%4];"
                 : "=r"(r0), "=r"(r1), "=r"(r2), "=r"(r3) : "r"(addr));
}
__device__ __forceinline__ void mma16816(float& d0, float& d1, float& d2, float& d3,
                                         unsigned a0, unsigned a1, unsigned a2, unsigned a3,
                                         unsigned b0, unsigned b1) {
    asm volatile(
        "mma.sync.aligned.m16n8k16.row.col.f32.f16.f16.f32 "
        "{%0,%1,%2,%3},{%4,%5,%6,%7},{%8,%9},{%0,%1,%2,%3};"
        : "+f"(d0), "+f"(d1), "+f"(d2), "+f"(d3)
        : "r"(a0), "r"(a1), "r"(a2), "r"(a3), "r"(b0), "r"(b1));
}

template <bool ALPHA, bool FMAX, bool AHALF>
__global__ __launch_bounds__(256) void gemm16_k(
    const void* __restrict__ Av, const float* __restrict__ A2,
    const float* __restrict__ ab, const float* __restrict__ B,
    const float* __restrict__ bias,
    const float* __restrict__ aS, const float* __restrict__ aD,
    float* __restrict__ pAS, float* __restrict__ pAD,
    void* __restrict__ Cv, int mbase, int M, int K, int Nc)
{
    __shared__ __half As[128][APAD];
    __shared__ __half Bs[32][BPAD];
    __shared__ float sPs[128];
    __shared__ float sPd[128];

    const int tid = threadIdx.x;
    const int lane = tid & 31;
    const int warp = tid >> 5;
    const int wm = warp & 3;
    const int wn = warp >> 2;
    const int m0 = mbase + blockIdx.y * 128;
    const int n0 = blockIdx.x * 64;

    float acc[2][4][4];
    #pragma unroll
    for (int mt = 0; mt < 2; mt++)
        #pragma unroll
        for (int nt = 0; nt < 4; nt++)
            #pragma unroll
            for (int r = 0; r < 4; r++) acc[mt][nt][r] = 0.f;

    if (ALPHA && tid < 128) { sPs[tid] = 0.f; sPd[tid] = 0.f; }

    float4 ra[4], ran[4];
    uint4 ra16[2], ran16[2];
    float4 rb[2], rbn[2];

    auto load_fragA = [&](int kt, float4 (&la)[4], uint4 (&la16)[2]) {
        if (AHALF) {
            const __half* Ah = (const __half*)Av;
            #pragma unroll
            for (int i = 0; i < 2; i++) {
                int q = tid + i * 256;
                int row = q >> 2;
                int ks = (q & 3) * 8;
                uint4 v = make_uint4(0, 0, 0, 0);
                if (m0 + row < M) {
                    v = *(const uint4*)(Ah + (size_t)(m0 + row) * K + kt + ks);
                    if (FMAX) {
                        const float* a2p = A2 + (size_t)(m0 + row) * K + kt + ks;
                        float4 a20 = *(const float4*)a2p;
                        float4 a21 = *(const float4*)(a2p + 4);
                        float4 b20 = *(const float4*)(ab + kt + ks);
                        float4 b21 = *(const float4*)(ab + kt + ks + 4);
                        float2 x0 = __half22float2(*(__half2*)&v.x);
                        float2 x1 = __half22float2(*(__half2*)&v.y);
                        float2 x2 = __half22float2(*(__half2*)&v.z);
                        float2 x3 = __half22float2(*(__half2*)&v.w);
                        __half2 h0 = __floats2half2_rn(fmaxf(x0.x, a20.x + b20.x),
                                                       fmaxf(x0.y, a20.y + b20.y));
                        __half2 h1 = __floats2half2_rn(fmaxf(x1.x, a20.z + b20.z),
                                                       fmaxf(x1.y, a20.w + b20.w));
                        __half2 h2 = __floats2half2_rn(fmaxf(x2.x, a21.x + b21.x),
                                                       fmaxf(x2.y, a21.y + b21.y));
                        __half2 h3 = __floats2half2_rn(fmaxf(x3.x, a21.z + b21.z),
                                                       fmaxf(x3.y, a21.w + b21.w));
                        v.x = *(unsigned*)&h0;
                        v.y = *(unsigned*)&h1;
                        v.z = *(unsigned*)&h2;
                        v.w = *(unsigned*)&h3;
                    }
                }
                la16[i] = v;
            }
        } else {
            const float* A = (const float*)Av;
            #pragma unroll
            for (int i = 0; i < 4; i++) {
                int q = tid + i * 256;
                int row = q >> 3;
                int ks = (q & 7) * 4;
                float4 v = make_float4(0.f, 0.f, 0.f, 0.f);
                if (m0 + row < M)
                    v = *(const float4*)(A + (size_t)(m0 + row) * K + kt + ks);
                la[i] = v;
            }
        }
    };
    auto load_fragB = [&](int kt, float4 (&lb)[2]) {
        #pragma unroll
        for (int i = 0; i < 2; i++) {
            int q = tid + i * 256;
            int kr = q >> 4;
            int ns = (q & 15) * 4;
            lb[i] = *(const float4*)(B + (size_t)(kt + kr) * Nc + n0 + ns);
        }
    };
    auto store_frag = [&](const float4 (&la)[4], const uint4 (&la16)[2],
                          const float4 (&lb)[2]) {
        if (AHALF) {
            #pragma unroll
            for (int i = 0; i < 2; i++) {
                int q = tid + i * 256;
                int row = q >> 2;
                int ks = (q & 3) * 8;
                *(uint4*)&As[row][ks] = la16[i];
            }
        } else {
            #pragma unroll
            for (int i = 0; i < 4; i++) {
                int q = tid + i * 256;
                int row = q >> 3;
                int ks = (q & 7) * 4;
                *(__half2*)&As[row][ks]     = __floats2half2_rn(la[i].x, la[i].y);
                *(__half2*)&As[row][ks + 2] = __floats2half2_rn(la[i].z, la[i].w);
            }
        }
        #pragma unroll
        for (int i = 0; i < 2; i++) {
            int q = tid + i * 256;
            int kr = q >> 4;
            int ns = (q & 15) * 4;
            *(__half2*)&Bs[kr][ns]     = __floats2half2_rn(lb[i].x, lb[i].y);
            *(__half2*)&Bs[kr][ns + 2] = __floats2half2_rn(lb[i].z, lb[i].w);
        }
    };

    load_fragA(0, ra, ra16);
    load_fragB(0, rb);

    for (int kt = 0; kt < K; kt += 32) {
        store_frag(ra, ra16, rb);
        __syncthreads();

        if (kt + 32 < K) {
            load_fragA(kt + 32, ran, ran16);
            load_fragB(kt + 32, rbn);
        }

        #pragma unroll
        for (int kg = 0; kg < 2; kg++) {
            unsigned a[2][4], bq[2][4];
            #pragma unroll
            for (int mt = 0; mt < 2; mt++) {
                unsigned ad = su32(&As[wm * 32 + mt * 16 + (lane & 15)]
                                      [kg * 16 + (lane >> 4) * 8]);
                ldm_x4(ad, a[mt][0], a[mt][1], a[mt][2], a[mt][3]);
            }
            #pragma unroll
            for (int np = 0; np < 2; np++) {
                unsigned bd = su32(&Bs[kg * 16 + (lane & 15)]
                                      [wn * 32 + np * 16 + (lane >> 4) * 8]);
                ldm_x4t(bd, bq[np][0], bq[np][1], bq[np][2], bq[np][3]);
            }
            #pragma unroll
            for (int mt = 0; mt < 2; mt++)
                #pragma unroll
                for (int nt = 0; nt < 4; nt++) {
                    unsigned b0 = bq[nt >> 1][(nt & 1) * 2];
                    unsigned b1 = bq[nt >> 1][(nt & 1) * 2 + 1];
                    mma16816(acc[mt][nt][0], acc[mt][nt][1],
                             acc[mt][nt][2], acc[mt][nt][3],
                             a[mt][0], a[mt][1], a[mt][2], a[mt][3], b0, b1);
                }
        }
        __syncthreads();

        #pragma unroll
        for (int i = 0; i < 4; i++) ra[i] = ran[i];
        #pragma unroll
        for (int i = 0; i < 2; i++) { ra16[i] = ran16[i]; rb[i] = rbn[i]; }
    }

    #pragma unroll
    for (int mt = 0; mt < 2; mt++) {
        int row0 = m0 + wm * 32 + mt * 16 + (lane >> 2);
        #pragma unroll
        for (int nt = 0; nt < 4; nt++) {
            int col = n0 + wn * 32 + nt * 8 + 2 * (lane & 3);
            if (ALPHA) {
                __half* C = (__half*)Cv;
                if (row0 < M)
                    *(__half2*)(C + (size_t)row0 * Nc + col) =
                        __floats2half2_rn(acc[mt][nt][0], acc[mt][nt][1]);
                if (row0 + 8 < M)
                    *(__half2*)(C + (size_t)(row0 + 8) * Nc + col) =
                        __floats2half2_rn(acc[mt][nt][2], acc[mt][nt][3]);
            } else {
                float* C = (float*)Cv;
                float2 bv = *(const float2*)(bias + col);
                if (row0 < M) {
                    float2 v = make_float2(acc[mt][nt][0] + bv.x, acc[mt][nt][1] + bv.y);
                    *(float2*)(C + (size_t)row0 * Nc + col) = v;
                }
                if (row0 + 8 < M) {
                    float2 v = make_float2(acc[mt][nt][2] + bv.x, acc[mt][nt][3] + bv.y);
                    *(float2*)(C + (size_t)(row0 + 8) * Nc + col) = v;
                }
            }
        }
    }

    if (ALPHA) {
        #pragma unroll
        for (int mt = 0; mt < 2; mt++) {
            float psg = 0.f, psg8 = 0.f, pdg = 0.f, pdg8 = 0.f;
            #pragma unroll
            for (int nt = 0; nt < 4; nt++) {
                int col = n0 + wn * 32 + nt * 8 + 2 * (lane & 3);
                float2 sv = *(const float2*)(aS + col);
                float2 dv = *(const float2*)(aD + col);
                psg  += acc[mt][nt][0] * sv.x + acc[mt][nt][1] * sv.y;
                psg8 += acc[mt][nt][2] * sv.x + acc[mt][nt][3] * sv.y;
                pdg  += acc[mt][nt][0] * dv.x + acc[mt][nt][1] * dv.y;
                pdg8 += acc[mt][nt][2] * dv.x + acc[mt][nt][3] * dv.y;
            }
            #pragma unroll
            for (int o = 1; o <= 2; o <<= 1) {
                psg  += __shfl_xor_sync(0xffffffffu, psg, o);
                psg8 += __shfl_xor_sync(0xffffffffu, psg8, o);
                pdg  += __shfl_xor_sync(0xffffffffu, pdg, o);
                pdg8 += __shfl_xor_sync(0xffffffffu, pdg8, o);
            }
            if ((lane & 3) == 0) {
                int rl = wm * 32 + mt * 16 + (lane >> 2);
                atomicAdd(&sPs[rl], psg);
                atomicAdd(&sPs[rl + 8], psg8);
                atomicAdd(&sPd[rl], pdg);
                atomicAdd(&sPd[rl + 8], pdg8);
            }
        }
        __syncthreads();
        if (tid < 128) {
            int row = m0 + tid;
            if (row < M) {
                int head = blockIdx.x;
                pAS[row * 4 + head] = sPs[tid];
                pAD[row * 4 + head] = sPd[tid];
            }
        }
    }
}

// ---------------- fused edge-softmax + CSR gather (fp16 features) ----------------
template <bool ACT>
__global__ __launch_bounds__(256) void gather_k(
    const __half* __restrict__ h, void* __restrict__ outv,
    const float* __restrict__ aS, const float* __restrict__ aD,
    const float* __restrict__ b0,
    const float* __restrict__ gamma,
    const float* __restrict__ beta, int nbase)
{
    int node = nbase + blockIdx.x * 8 + (threadIdx.x >> 5);
    if (node >= NN) return;
    int t = threadIdx.x & 31;
    int head = t >> 3;
    int oct = t & 7;
    int p = g_off[node];
    const int end = g_off[node + 1];

    const float ad = aD[node * 4 + head];
    float a[8];
    #pragma unroll
    for (int i = 0; i < 8; i++) a[i] = 0.f;
    float wsum = 0.f;

    const int coff = head * 64 + oct * 8;

    for (; p + 4 <= end; p += 4) {
        int s0 = g_adj[p + 0];
        int s1 = g_adj[p + 1];
        int s2 = g_adj[p + 2];
        int s3 = g_adj[p + 3];
        float e0 = aS[s0 * 4 + head] + ad;
        float e1 = aS[s1 * 4 + head] + ad;
        float e2 = aS[s2 * 4 + head] + ad;
        float e3 = aS[s3 * 4 + head] + ad;
        uint4 r0 = __ldcg((const uint4*)(h + (size_t)s0 * HC + coff));
        uint4 r1 = __ldcg((const uint4*)(h + (size_t)s1 * HC + coff));
        uint4 r2 = __ldcg((const uint4*)(h + (size_t)s2 * HC + coff));
        uint4 r3 = __ldcg((const uint4*)(h + (size_t)s3 * HC + coff));
        e0 = e0 > 0.f ? e0 : 0.2f * e0;
        e1 = e1 > 0.f ? e1 : 0.2f * e1;
        e2 = e2 > 0.f ? e2 : 0.2f * e2;
        e3 = e3 > 0.f ? e3 : 0.2f * e3;
        float w0 = __expf(e0), w1 = __expf(e1), w2 = __expf(e2), w3 = __expf(e3);
        wsum += (w0 + w1) + (w2 + w3);
        const uint4* rr[4] = {&r0, &r1, &r2, &r3};
        float ww[4] = {w0, w1, w2, w3};
        #pragma unroll
        for (int u = 0; u < 4; u++) {
            float2 f0 = __half22float2(*(const __half2*)&rr[u]->x);
            float2 f1 = __half22float2(*(const __half2*)&rr[u]->y);
            float2 f2 = __half22float2(*(const __half2*)&rr[u]->z);
            float2 f3 = __half22float2(*(const __half2*)&rr[u]->w);
            float w = ww[u];
            a[0] = fmaf(w, f0.x, a[0]);
            a[1] = fmaf(w, f0.y, a[1]);
            a[2] = fmaf(w, f1.x, a[2]);
            a[3] = fmaf(w, f1.y, a[3]);
            a[4] = fmaf(w, f2.x, a[4]);
            a[5] = fmaf(w, f2.y, a[5]);
            a[6] = fmaf(w, f3.x, a[6]);
            a[7] = fmaf(w, f3.y, a[7]);
        }
    }
    for (; p < end; p++) {
        int s = g_adj[p];
        float e = aS[s * 4 + head] + ad;
        e = e > 0.f ? e : 0.2f * e;
        float w = __expf(e);
        uint4 raw = __ldcg((const uint4*)(h + (size_t)s * HC + coff));
        float2 f0 = __half22float2(*(__half2*)&raw.x);
        float2 f1 = __half22float2(*(__half2*)&raw.y);
        float2 f2 = __half22float2(*(__half2*)&raw.z);
        float2 f3 = __half22float2(*(__half2*)&raw.w);
        a[0] = fmaf(w, f0.x, a[0]);
        a[1] = fmaf(w, f0.y, a[1]);
        a[2] = fmaf(w, f1.x, a[2]);
        a[3] = fmaf(w, f1.y, a[3]);
        a[4] = fmaf(w, f2.x, a[4]);
        a[5] = fmaf(w, f2.y, a[5]);
        a[6] = fmaf(w, f3.x, a[6]);
        a[7] = fmaf(w, f3.y, a[7]);
        wsum += w;
    }

    float inv = 1.0f / (wsum + 1e-16f);
    #pragma unroll
    for (int i = 0; i < 8; i++) a[i] *= inv;

    if (ACT) {
        const float r = rsqrtf(1.0f + 1e-5f);
        float v[8];
        #pragma unroll
        for (int u = 0; u < 2; u++) {
            float4 bb = *(const float4*)(b0 + coff + u * 4);
            float4 gg = *(const float4*)(gamma + coff + u * 4);
            float4 be = *(const float4*)(beta + coff + u * 4);
            float v0 = (a[u * 4 + 0] + bb.x) * (gg.x * r) + be.x;
            float v1 = (a[u * 4 + 1] + bb.y) * (gg.y * r) + be.y;
            float v2 = (a[u * 4 + 2] + bb.z) * (gg.z * r) + be.z;
            float v3 = (a[u * 4 + 3] + bb.w) * (gg.w * r) + be.w;
            v[u * 4 + 0] = v0 > 0.f ? v0 : expm1f(v0);
            v[u * 4 + 1] = v1 > 0.f ? v1 : expm1f(v1);
            v[u * 4 + 2] = v2 > 0.f ? v2 : expm1f(v2);
            v[u * 4 + 3] = v3 > 0.f ? v3 : expm1f(v3);
        }
        __half2 h0 = __floats2half2_rn(v[0], v[1]);
        __half2 h1 = __floats2half2_rn(v[2], v[3]);
        __half2 h2 = __floats2half2_rn(v[4], v[5]);
        __half2 h3 = __floats2half2_rn(v[6], v[7]);
        uint4 pk;
        pk.x = *(unsigned*)&h0;
        pk.y = *(unsigned*)&h1;
        pk.z = *(unsigned*)&h2;
        pk.w = *(unsigned*)&h3;
        *(uint4*)((__half*)outv + (size_t)node * HC + coff) = pk;
    } else {
        float* op = (float*)outv + (size_t)node * HC + coff;
        *(float4*)op = make_float4(a[0], a[1], a[2], a[3]);
        *(float4*)(op + 4) = make_float4(a[4], a[5], a[6], a[7]);
    }
}

// ---------------- launch ----------------
extern "C" void kernel_launch(void* const* d_in, const int* in_sizes, int n_in,
                              void* d_out, int out_size)
{
    const float* x      = (const float*)d_in[0];
    const void*  ei     = d_in[1];
    const float* W0     = (const float*)d_in[2];
    const float* as0    = (const float*)d_in[3];
    const float* ad0    = (const float*)d_in[4];
    const float* b0     = (const float*)d_in[5];
    const float* gamma0 = (const float*)d_in[6];
    const float* beta0  = (const float*)d_in[7];
    const float* W1     = (const float*)d_in[8];
    const float* as1    = (const float*)d_in[9];
    const float* ad1    = (const float*)d_in[10];
    const float* b1     = (const float*)d_in[11];
    const float* Wf     = (const float*)d_in[12];
    const float* bf     = (const float*)d_in[13];
    float* out = (float*)d_out;

    __half *h, *h2, *x1;
    float *acc, *pas0, *pad0, *pas1, *pad1;
    cudaGetSymbolAddress((void**)&h,    g_h);
    cudaGetSymbolAddress((void**)&h2,   g_h2);
    cudaGetSymbolAddress((void**)&x1,   g_x1);
    cudaGetSymbolAddress((void**)&acc,  g_acc);
    cudaGetSymbolAddress((void**)&pas0, g_asrc);
    cudaGetSymbolAddress((void**)&pad0, g_adst);
    cudaGetSymbolAddress((void**)&pas1, g_as1);
    cudaGetSymbolAddress((void**)&pad1, g_ad1);

    static cudaStream_t s2 = nullptr;
    static cudaEvent_t evFork = nullptr, evJoin = nullptr;
    static cudaEvent_t evA[NCHUNK], evB[NCHUNK], evC[NCHUNK], evD[NCHUNK];
    if (s2 == nullptr) {
        cudaStreamCreateWithFlags(&s2, cudaStreamNonBlocking);
        cudaEventCreateWithFlags(&evFork, cudaEventDisableTiming);
        cudaEventCreateWithFlags(&evJoin, cudaEventDisableTiming);
        for (int c = 0; c < NCHUNK; c++) {
            cudaEventCreateWithFlags(&evA[c], cudaEventDisableTiming);
            cudaEventCreateWithFlags(&evB[c], cudaEventDisableTiming);
            cudaEventCreateWithFlags(&evC[c], cudaEventDisableTiming);
            cudaEventCreateWithFlags(&evD[c], cudaEventDisableTiming);
        }
    }

    const int mb = (NN + 127) / 128;
    const int hb = (NE / 4 + 255) / 256;
    const int fb = (NE / 2 + 255) / 256;

    int rbound[NCHUNK + 1];
    for (int c = 0; c <= NCHUNK; c++) {
        int r = c * CROWS;
        rbound[c] = r < NN ? r : NN;
    }

    // ---- fork: CSR build on s2, concurrent with GEMM0 ----
    cudaEventRecord(evFork, 0);
    cudaStreamWaitEvent(s2, evFork, 0);

    zerodetect_k<<<(NN + 255) / 256, 256, 0, s2>>>((const int*)ei);
    hist_k<<<hb, 256, 0, s2>>>(ei);
    scan1_k<<<NB_SCAN, 256, 0, s2>>>();
    scan2_k<<<1, 256, 0, s2>>>();
    scan3_k<<<NB_SCAN, 256, 0, s2>>>();
    fill_k<<<fb, 256, 0, s2>>>(ei);
    cudaEventRecord(evJoin, s2);

    // ---- layer 0 GEMM (full) -> h, alpha set 0 ----
    gemm16_k<true, false, false><<<dim3(HC / 64, mb), 256>>>(
        x, nullptr, nullptr, W0, nullptr, as0, ad0, pas0, pad0, h, 0, NN, 128, HC);

    cudaStreamWaitEvent(0, evJoin, 0);

    // ---- pipelined: gather0 chunk c (stream 0, reads h/alpha0)
    //                 -> GEMM1 chunk c (s2, writes h2/alpha1) — disjoint buffers ----
    for (int c = 0; c < NCHUNK; c++) {
        int n0r = rbound[c], n1r = rbound[c + 1];
        int gblk = (n1r - n0r + 7) / 8;
        gather_k<true><<<gblk, 256>>>(h, x1, pas0, pad0, b0, gamma0, beta0, n0r);
        cudaEventRecord(evA[c], 0);
        cudaStreamWaitEvent(s2, evA[c], 0);
        int yb = (n1r - n0r + 127) / 128;
        gemm16_k<true, false, true><<<dim3(HC / 64, yb), 256, 0, s2>>>(
            x1, nullptr, nullptr, W1, nullptr, as1, ad1, pas1, pad1, h2, n0r, NN, HC, HC);
        cudaEventRecord(evB[c], s2);
    }
    // gather1 needs ALL of GEMM1 (random src access)
    for (int c = 0; c < NCHUNK; c++) cudaStreamWaitEvent(0, evB[c], 0);

    // ---- pipelined: gather1 chunk c (stream 0, reads h2/alpha1, writes acc)
    //                 -> gemmf chunk c (s2, reads x1+acc rows of chunk) ----
    for (int c = 0; c < NCHUNK; c++) {
        int n0r = rbound[c], n1r = rbound[c + 1];
        int gblk = (n1r - n0r + 7) / 8;
        gather_k<false><<<gblk, 256>>>(h2, acc, pas1, pad1, nullptr, nullptr, nullptr, n0r);
        cudaEventRecord(evC[c], 0);
        cudaStreamWaitEvent(s2, evC[c], 0);
        int yb = (n1r - n0r + 127) / 128;
        gemm16_k<false, true, true><<<dim3(1, yb), 256, 0, s2>>>(
            x1, acc, b1, Wf, bf, nullptr, nullptr, nullptr, nullptr, out, n0r, NN, HC, 64);
        cudaEventRecord(evD[c], s2);
    }
    for (int c = 0; c < NCHUNK; c++) cudaStreamWaitEvent(0, evD[c], 0);
}

// round 15
// speedup vs baseline: 1.1332x; 1.1332x over previous
#include <cuda_runtime.h>
#include <cuda_fp16.h>
#include <math.h>

#define NN 50000
#define NE 800000
#define NET (NE + NN)       // edges + self loops = 850000
#define HC 256              // H*C
#define NH 4
#define CC 64
#define NB_SCAN 196         // ceil(NN/256)

// ---------------- scratch (static device globals; no allocs) ----------------
__device__ __align__(16) __half g_h[NN * HC];     // transformed features (fp16, per layer)
__device__ __align__(16) __half g_x1[NN * HC];    // layer-0 activated output (fp16)
__device__ __align__(16) float g_acc[NN * HC];    // layer-1 aggregation output (fp32)
__device__ __align__(16) float g_asrc[NN * NH];
__device__ __align__(16) float g_adst[NN * NH];
__device__ int g_deg[NN];
__device__ int g_off[NN + 1];
__device__ int g_cur[NN];
__device__ int g_part[NB_SCAN];
__device__ int g_adj[NET];                        // src ids grouped by dst
__device__ int g_is64;

// ---------------- zero deg (=1: self-loop pre-counted) + detect dtype ----------------
__global__ void zerodetect_k(const int* ei32) {
    int i = blockIdx.x * blockDim.x + threadIdx.x;
    if (i < NN) g_deg[i] = 1;
    if (i == 0) {
        int ok = 1;
        #pragma unroll
        for (int k = 0; k < 64; k++)
            if (ei32[2 * k + 1] != 0) ok = 0;
        g_is64 = ok;
    }
}

// ---------------- CSR build (real edges only; self-loops planted by scan23) ----------------
// histogram over destinations, 4 edges per thread (vectorized)
__global__ void hist_k(const void* __restrict__ ei) {
    int q = blockIdx.x * blockDim.x + threadIdx.x;
    int e = q * 4;
    if (e >= NE) return;
    int d0, d1, d2, d3;
    if (g_is64) {
        const longlong2* p = (const longlong2*)((const long long*)ei + NE);
        longlong2 a = p[q * 2];
        longlong2 b = p[q * 2 + 1];
        d0 = (int)a.x; d1 = (int)a.y; d2 = (int)b.x; d3 = (int)b.y;
    } else {
        int4 a = ((const int4*)((const int*)ei + NE))[q];
        d0 = a.x; d1 = a.y; d2 = a.z; d3 = a.w;
    }
    atomicAdd(&g_deg[d0], 1);
    atomicAdd(&g_deg[d1], 1);
    atomicAdd(&g_deg[d2], 1);
    atomicAdd(&g_deg[d3], 1);
}

__global__ void scan1_k() {
    __shared__ int sh[256];
    int i = blockIdx.x * 256 + threadIdx.x;
    int v = (i < NN) ? g_deg[i] : 0;
    sh[threadIdx.x] = v; __syncthreads();
    for (int o = 128; o; o >>= 1) {
        if (threadIdx.x < o) sh[threadIdx.x] += sh[threadIdx.x + o];
        __syncthreads();
    }
    if (threadIdx.x == 0) g_part[blockIdx.x] = sh[0];
}

// merged scan2+scan3: each block reduces its own prefix of g_part, then does
// the per-block exclusive scan, writes off/cur and plants the self-loop.
__global__ void scan23_k() {
    __shared__ int sh[256];
    __shared__ int base;
    const int t = threadIdx.x;

    // phase 1: base = sum of g_part[0 .. blockIdx.x-1]  (NB_SCAN=196 < 256)
    int v = (t < blockIdx.x && t < NB_SCAN) ? g_part[t] : 0;
    sh[t] = v; __syncthreads();
    for (int o = 128; o; o >>= 1) {
        if (t < o) sh[t] += sh[t + o];
        __syncthreads();
    }
    if (t == 0) base = sh[0];
    __syncthreads();

    // phase 2: per-block inclusive scan of deg
    int i = blockIdx.x * 256 + t;
    int d = (i < NN) ? g_deg[i] : 0;
    sh[t] = d; __syncthreads();
    for (int o = 1; o < 256; o <<= 1) {
        int x = (t >= o) ? sh[t - o] : 0;
        __syncthreads();
        sh[t] += x;
        __syncthreads();
    }
    if (i < NN) {
        int off = base + sh[t] - d;
        g_off[i] = off;
        g_adj[off] = i;          // plant self-loop in first slot
        g_cur[i] = off + 1;      // real edges fill after it
        if (i == NN - 1) g_off[NN] = off + d;
    }
}

// fill real edges, 2 per thread (vectorized)
__global__ void fill_k(const void* __restrict__ ei) {
    int q = blockIdx.x * blockDim.x + threadIdx.x;
    int e = q * 2;
    if (e >= NE) return;
    int s0, s1, d0, d1;
    if (g_is64) {
        const long long* p = (const long long*)ei;
        longlong2 sv = ((const longlong2*)p)[q];
        longlong2 dv = ((const longlong2*)(p + NE))[q];
        s0 = (int)sv.x; s1 = (int)sv.y;
        d0 = (int)dv.x; d1 = (int)dv.y;
    } else {
        const int* p = (const int*)ei;
        int2 sv = ((const int2*)p)[q];
        int2 dv = ((const int2*)(p + NE))[q];
        s0 = sv.x; s1 = sv.y;
        d0 = dv.x; d1 = dv.y;
    }
    int p0 = atomicAdd(&g_cur[d0], 1);
    g_adj[p0] = s0;
    int p1 = atomicAdd(&g_cur[d1], 1);
    g_adj[p1] = s1;
}

// ---------------- tensor-core GEMM (fp16 HMMA, fp32 accum) ----------------
// ALPHA: fp16 output + per-row alpha dots (head = blockIdx.x).
// FMAX:  A-element = max(A, A2 + ab); fp32 output with +bias (final projection).
// AHALF: A operand is fp16 in global memory.
#define APAD 40
#define BPAD 72
__device__ __forceinline__ unsigned su32(const void* p) {
    return (unsigned)__cvta_generic_to_shared(p);
}
__device__ __forceinline__ void ldm_x4(unsigned addr, unsigned& r0, unsigned& r1,
                                       unsigned& r2, unsigned& r3) {
    asm volatile("ldmatrix.sync.aligned.m8n8.x4.shared.b16 {%0,%1,%2,%3},[%4];"
                 : "=r"(r0), "=r"(r1), "=r"(r2), "=r"(r3) : "r"(addr));
}
__device__ __forceinline__ void ldm_x4t(unsigned addr, unsigned& r0, unsigned& r1,
                                        unsigned& r2, unsigned& r3) {
    asm volatile("ldmatrix.sync.aligned.m8n8.x4.trans.shared.b16 {%0,%1,%2,%3},[%4];"
                 : "=r"(r0), "=r"(r1), "=r"(r2), "=r"(r3) : "r"(addr));
}
__device__ __forceinline__ void mma16816(float& d0, float& d1, float& d2, float& d3,
                                         unsigned a0, unsigned a1, unsigned a2, unsigned a3,
                                         unsigned b0, unsigned b1) {
    asm volatile(
        "mma.sync.aligned.m16n8k16.row.col.f32.f16.f16.f32 "
        "{%0,%1,%2,%3},{%4,%5,%6,%7},{%8,%9},{%0,%1,%2,%3};"
        : "+f"(d0), "+f"(d1), "+f"(d2), "+f"(d3)
        : "r"(a0), "r"(a1), "r"(a2), "r"(a3), "r"(b0), "r"(b1));
}

template <bool ALPHA, bool FMAX, bool AHALF>
__global__ __launch_bounds__(256) void gemm16_k(
    const void* __restrict__ Av, const float* __restrict__ A2,
    const float* __restrict__ ab, const float* __restrict__ B,
    const float* __restrict__ bias,
    const float* __restrict__ aS, const float* __restrict__ aD,
    void* __restrict__ Cv, int M, int K, int Nc)
{
    __shared__ __half As[128][APAD];
    __shared__ __half Bs[32][BPAD];
    __shared__ float sPs[128];
    __shared__ float sPd[128];

    const int tid = threadIdx.x;
    const int lane = tid & 31;
    const int warp = tid >> 5;
    const int wm = warp & 3;
    const int wn = warp >> 2;
    const int m0 = blockIdx.y * 128;
    const int n0 = blockIdx.x * 64;

    float acc[2][4][4];
    #pragma unroll
    for (int mt = 0; mt < 2; mt++)
        #pragma unroll
        for (int nt = 0; nt < 4; nt++)
            #pragma unroll
            for (int r = 0; r < 4; r++) acc[mt][nt][r] = 0.f;

    if (ALPHA && tid < 128) { sPs[tid] = 0.f; sPd[tid] = 0.f; }

    float4 ra[4], ran[4];
    uint4 ra16[2], ran16[2];
    float4 rb[2], rbn[2];

    auto load_fragA = [&](int kt, float4 (&la)[4], uint4 (&la16)[2]) {
        if (AHALF) {
            const __half* Ah = (const __half*)Av;
            #pragma unroll
            for (int i = 0; i < 2; i++) {
                int q = tid + i * 256;
                int row = q >> 2;
                int ks = (q & 3) * 8;
                uint4 v = make_uint4(0, 0, 0, 0);
                if (m0 + row < M) {
                    v = *(const uint4*)(Ah + (size_t)(m0 + row) * K + kt + ks);
                    if (FMAX) {
                        const float* a2p = A2 + (size_t)(m0 + row) * K + kt + ks;
                        float4 a20 = *(const float4*)a2p;
                        float4 a21 = *(const float4*)(a2p + 4);
                        float4 b20 = *(const float4*)(ab + kt + ks);
                        float4 b21 = *(const float4*)(ab + kt + ks + 4);
                        float2 x0 = __half22float2(*(__half2*)&v.x);
                        float2 x1 = __half22float2(*(__half2*)&v.y);
                        float2 x2 = __half22float2(*(__half2*)&v.z);
                        float2 x3 = __half22float2(*(__half2*)&v.w);
                        __half2 h0 = __floats2half2_rn(fmaxf(x0.x, a20.x + b20.x),
                                                       fmaxf(x0.y, a20.y + b20.y));
                        __half2 h1 = __floats2half2_rn(fmaxf(x1.x, a20.z + b20.z),
                                                       fmaxf(x1.y, a20.w + b20.w));
                        __half2 h2 = __floats2half2_rn(fmaxf(x2.x, a21.x + b21.x),
                                                       fmaxf(x2.y, a21.y + b21.y));
                        __half2 h3 = __floats2half2_rn(fmaxf(x3.x, a21.z + b21.z),
                                                       fmaxf(x3.y, a21.w + b21.w));
                        v.x = *(unsigned*)&h0;
                        v.y = *(unsigned*)&h1;
                        v.z = *(unsigned*)&h2;
                        v.w = *(unsigned*)&h3;
                    }
                }
                la16[i] = v;
            }
        } else {
            const float* A = (const float*)Av;
            #pragma unroll
            for (int i = 0; i < 4; i++) {
                int q = tid + i * 256;
                int row = q >> 3;
                int ks = (q & 7) * 4;
                float4 v = make_float4(0.f, 0.f, 0.f, 0.f);
                if (m0 + row < M)
                    v = *(const float4*)(A + (size_t)(m0 + row) * K + kt + ks);
                la[i] = v;
            }
        }
    };
    auto load_fragB = [&](int kt, float4 (&lb)[2]) {
        #pragma unroll
        for (int i = 0; i < 2; i++) {
            int q = tid + i * 256;
            int kr = q >> 4;
            int ns = (q & 15) * 4;
            lb[i] = *(const float4*)(B + (size_t)(kt + kr) * Nc + n0 + ns);
        }
    };
    auto store_frag = [&](const float4 (&la)[4], const uint4 (&la16)[2],
                          const float4 (&lb)[2]) {
        if (AHALF) {
            #pragma unroll
            for (int i = 0; i < 2; i++) {
                int q = tid + i * 256;
                int row = q >> 2;
                int ks = (q & 3) * 8;
                *(uint4*)&As[row][ks] = la16[i];
            }
        } else {
            #pragma unroll
            for (int i = 0; i < 4; i++) {
                int q = tid + i * 256;
                int row = q >> 3;
                int ks = (q & 7) * 4;
                *(__half2*)&As[row][ks]     = __floats2half2_rn(la[i].x, la[i].y);
                *(__half2*)&As[row][ks + 2] = __floats2half2_rn(la[i].z, la[i].w);
            }
        }
        #pragma unroll
        for (int i = 0; i < 2; i++) {
            int q = tid + i * 256;
            int kr = q >> 4;
            int ns = (q & 15) * 4;
            *(__half2*)&Bs[kr][ns]     = __floats2half2_rn(lb[i].x, lb[i].y);
            *(__half2*)&Bs[kr][ns + 2] = __floats2half2_rn(lb[i].z, lb[i].w);
        }
    };

    load_fragA(0, ra, ra16);
    load_fragB(0, rb);

    for (int kt = 0; kt < K; kt += 32) {
        store_frag(ra, ra16, rb);
        __syncthreads();

        if (kt + 32 < K) {
            load_fragA(kt + 32, ran, ran16);
            load_fragB(kt + 32, rbn);
        }

        #pragma unroll
        for (int kg = 0; kg < 2; kg++) {
            unsigned a[2][4], bq[2][4];
            #pragma unroll
            for (int mt = 0; mt < 2; mt++) {
                unsigned ad = su32(&As[wm * 32 + mt * 16 + (lane & 15)]
                                      [kg * 16 + (lane >> 4) * 8]);
                ldm_x4(ad, a[mt][0], a[mt][1], a[mt][2], a[mt][3]);
            }
            #pragma unroll
            for (int np = 0; np < 2; np++) {
                unsigned bd = su32(&Bs[kg * 16 + (lane & 15)]
                                      [wn * 32 + np * 16 + (lane >> 4) * 8]);
                ldm_x4t(bd, bq[np][0], bq[np][1], bq[np][2], bq[np][3]);
            }
            #pragma unroll
            for (int mt = 0; mt < 2; mt++)
                #pragma unroll
                for (int nt = 0; nt < 4; nt++) {
                    unsigned b0 = bq[nt >> 1][(nt & 1) * 2];
                    unsigned b1 = bq[nt >> 1][(nt & 1) * 2 + 1];
                    mma16816(acc[mt][nt][0], acc[mt][nt][1],
                             acc[mt][nt][2], acc[mt][nt][3],
                             a[mt][0], a[mt][1], a[mt][2], a[mt][3], b0, b1);
                }
        }
        __syncthreads();

        #pragma unroll
        for (int i = 0; i < 4; i++) ra[i] = ran[i];
        #pragma unroll
        for (int i = 0; i < 2; i++) { ra16[i] = ran16[i]; rb[i] = rbn[i]; }
    }

    #pragma unroll
    for (int mt = 0; mt < 2; mt++) {
        int row0 = m0 + wm * 32 + mt * 16 + (lane >> 2);
        #pragma unroll
        for (int nt = 0; nt < 4; nt++) {
            int col = n0 + wn * 32 + nt * 8 + 2 * (lane & 3);
            if (ALPHA) {
                __half* C = (__half*)Cv;
                if (row0 < M)
                    *(__half2*)(C + (size_t)row0 * Nc + col) =
                        __floats2half2_rn(acc[mt][nt][0], acc[mt][nt][1]);
                if (row0 + 8 < M)
                    *(__half2*)(C + (size_t)(row0 + 8) * Nc + col) =
                        __floats2half2_rn(acc[mt][nt][2], acc[mt][nt][3]);
            } else {
                float* C = (float*)Cv;
                float2 bv = *(const float2*)(bias + col);
                if (row0 < M) {
                    float2 v = make_float2(acc[mt][nt][0] + bv.x, acc[mt][nt][1] + bv.y);
                    *(float2*)(C + (size_t)row0 * Nc + col) = v;
                }
                if (row0 + 8 < M) {
                    float2 v = make_float2(acc[mt][nt][2] + bv.x, acc[mt][nt][3] + bv.y);
                    *(float2*)(C + (size_t)(row0 + 8) * Nc + col) = v;
                }
            }
        }
    }

    if (ALPHA) {
        #pragma unroll
        for (int mt = 0; mt < 2; mt++) {
            float psg = 0.f, psg8 = 0.f, pdg = 0.f, pdg8 = 0.f;
            #pragma unroll
            for (int nt = 0; nt < 4; nt++) {
                int col = n0 + wn * 32 + nt * 8 + 2 * (lane & 3);
                float2 sv = *(const float2*)(aS + col);
                float2 dv = *(const float2*)(aD + col);
                psg  += acc[mt][nt][0] * sv.x + acc[mt][nt][1] * sv.y;
                psg8 += acc[mt][nt][2] * sv.x + acc[mt][nt][3] * sv.y;
                pdg  += acc[mt][nt][0] * dv.x + acc[mt][nt][1] * dv.y;
                pdg8 += acc[mt][nt][2] * dv.x + acc[mt][nt][3] * dv.y;
            }
            #pragma unroll
            for (int o = 1; o <= 2; o <<= 1) {
                psg  += __shfl_xor_sync(0xffffffffu, psg, o);
                psg8 += __shfl_xor_sync(0xffffffffu, psg8, o);
                pdg  += __shfl_xor_sync(0xffffffffu, pdg, o);
                pdg8 += __shfl_xor_sync(0xffffffffu, pdg8, o);
            }
            if ((lane & 3) == 0) {
                int rl = wm * 32 + mt * 16 + (lane >> 2);
                atomicAdd(&sPs[rl], psg);
                atomicAdd(&sPs[rl + 8], psg8);
                atomicAdd(&sPd[rl], pdg);
                atomicAdd(&sPd[rl + 8], pdg8);
            }
        }
        __syncthreads();
        if (tid < 128) {
            int row = m0 + tid;
            if (row < M) {
                int head = blockIdx.x;
                g_asrc[row * 4 + head] = sPs[tid];
                g_adst[row * 4 + head] = sPd[tid];
            }
        }
    }
}

// ---------------- fused edge-softmax + CSR gather (fp16 features) ----------------
// R7/R12 champion shape: 32 threads per node, 8 nodes per block, 4x unrolled, __ldcg.
// ACT=true: bias + BN(eval) + ELU epilogue, OUTPUT fp16 (x1). ACT=false: fp32 out.
template <bool ACT>
__global__ __launch_bounds__(256) void gather_k(
    const __half* __restrict__ h, void* __restrict__ outv,
    const float* __restrict__ b0,
    const float* __restrict__ gamma,
    const float* __restrict__ beta)
{
    int node = blockIdx.x * 8 + (threadIdx.x >> 5);
    if (node >= NN) return;
    int t = threadIdx.x & 31;
    int head = t >> 3;
    int oct = t & 7;
    int p = g_off[node];
    const int end = g_off[node + 1];

    const float ad = g_adst[node * 4 + head];
    float a[8];
    #pragma unroll
    for (int i = 0; i < 8; i++) a[i] = 0.f;
    float wsum = 0.f;

    const int coff = head * 64 + oct * 8;

    for (; p + 4 <= end; p += 4) {
        int s0 = g_adj[p + 0];
        int s1 = g_adj[p + 1];
        int s2 = g_adj[p + 2];
        int s3 = g_adj[p + 3];
        float e0 = g_asrc[s0 * 4 + head] + ad;
        float e1 = g_asrc[s1 * 4 + head] + ad;
        float e2 = g_asrc[s2 * 4 + head] + ad;
        float e3 = g_asrc[s3 * 4 + head] + ad;
        uint4 r0 = __ldcg((const uint4*)(h + (size_t)s0 * HC + coff));
        uint4 r1 = __ldcg((const uint4*)(h + (size_t)s1 * HC + coff));
        uint4 r2 = __ldcg((const uint4*)(h + (size_t)s2 * HC + coff));
        uint4 r3 = __ldcg((const uint4*)(h + (size_t)s3 * HC + coff));
        e0 = e0 > 0.f ? e0 : 0.2f * e0;
        e1 = e1 > 0.f ? e1 : 0.2f * e1;
        e2 = e2 > 0.f ? e2 : 0.2f * e2;
        e3 = e3 > 0.f ? e3 : 0.2f * e3;
        float w0 = __expf(e0), w1 = __expf(e1), w2 = __expf(e2), w3 = __expf(e3);
        wsum += (w0 + w1) + (w2 + w3);
        const uint4* rr[4] = {&r0, &r1, &r2, &r3};
        float ww[4] = {w0, w1, w2, w3};
        #pragma unroll
        for (int u = 0; u < 4; u++) {
            float2 f0 = __half22float2(*(const __half2*)&rr[u]->x);
            float2 f1 = __half22float2(*(const __half2*)&rr[u]->y);
            float2 f2 = __half22float2(*(const __half2*)&rr[u]->z);
            float2 f3 = __half22float2(*(const __half2*)&rr[u]->w);
            float w = ww[u];
            a[0] = fmaf(w, f0.x, a[0]);
            a[1] = fmaf(w, f0.y, a[1]);
            a[2] = fmaf(w, f1.x, a[2]);
            a[3] = fmaf(w, f1.y, a[3]);
            a[4] = fmaf(w, f2.x, a[4]);
            a[5] = fmaf(w, f2.y, a[5]);
            a[6] = fmaf(w, f3.x, a[6]);
            a[7] = fmaf(w, f3.y, a[7]);
        }
    }
    for (; p < end; p++) {
        int s = g_adj[p];
        float e = g_asrc[s * 4 + head] + ad;
        e = e > 0.f ? e : 0.2f * e;
        float w = __expf(e);
        uint4 raw = __ldcg((const uint4*)(h + (size_t)s * HC + coff));
        float2 f0 = __half22float2(*(__half2*)&raw.x);
        float2 f1 = __half22float2(*(__half2*)&raw.y);
        float2 f2 = __half22float2(*(__half2*)&raw.z);
        float2 f3 = __half22float2(*(__half2*)&raw.w);
        a[0] = fmaf(w, f0.x, a[0]);
        a[1] = fmaf(w, f0.y, a[1]);
        a[2] = fmaf(w, f1.x, a[2]);
        a[3] = fmaf(w, f1.y, a[3]);
        a[4] = fmaf(w, f2.x, a[4]);
        a[5] = fmaf(w, f2.y, a[5]);
        a[6] = fmaf(w, f3.x, a[6]);
        a[7] = fmaf(w, f3.y, a[7]);
        wsum += w;
    }

    float inv = 1.0f / (wsum + 1e-16f);
    #pragma unroll
    for (int i = 0; i < 8; i++) a[i] *= inv;

    if (ACT) {
        const float r = rsqrtf(1.0f + 1e-5f);
        float v[8];
        #pragma unroll
        for (int u = 0; u < 2; u++) {
            float4 bb = *(const float4*)(b0 + coff + u * 4);
            float4 gg = *(const float4*)(gamma + coff + u * 4);
            float4 be = *(const float4*)(beta + coff + u * 4);
            float v0 = (a[u * 4 + 0] + bb.x) * (gg.x * r) + be.x;
            float v1 = (a[u * 4 + 1] + bb.y) * (gg.y * r) + be.y;
            float v2 = (a[u * 4 + 2] + bb.z) * (gg.z * r) + be.z;
            float v3 = (a[u * 4 + 3] + bb.w) * (gg.w * r) + be.w;
            v[u * 4 + 0] = v0 > 0.f ? v0 : expm1f(v0);
            v[u * 4 + 1] = v1 > 0.f ? v1 : expm1f(v1);
            v[u * 4 + 2] = v2 > 0.f ? v2 : expm1f(v2);
            v[u * 4 + 3] = v3 > 0.f ? v3 : expm1f(v3);
        }
        __half2 h0 = __floats2half2_rn(v[0], v[1]);
        __half2 h1 = __floats2half2_rn(v[2], v[3]);
        __half2 h2 = __floats2half2_rn(v[4], v[5]);
        __half2 h3 = __floats2half2_rn(v[6], v[7]);
        uint4 pk;
        pk.x = *(unsigned*)&h0;
        pk.y = *(unsigned*)&h1;
        pk.z = *(unsigned*)&h2;
        pk.w = *(unsigned*)&h3;
        *(uint4*)((__half*)outv + (size_t)node * HC + coff) = pk;
    } else {
        float* op = (float*)outv + (size_t)node * HC + coff;
        *(float4*)op = make_float4(a[0], a[1], a[2], a[3]);
        *(float4*)(op + 4) = make_float4(a[4], a[5], a[6], a[7]);
    }
}

// ---------------- launch ----------------
extern "C" void kernel_launch(void* const* d_in, const int* in_sizes, int n_in,
                              void* d_out, int out_size)
{
    const float* x      = (const float*)d_in[0];
    const void*  ei     = d_in[1];
    const float* W0     = (const float*)d_in[2];
    const float* as0    = (const float*)d_in[3];
    const float* ad0    = (const float*)d_in[4];
    const float* b0     = (const float*)d_in[5];
    const float* gamma0 = (const float*)d_in[6];
    const float* beta0  = (const float*)d_in[7];
    const float* W1     = (const float*)d_in[8];
    const float* as1    = (const float*)d_in[9];
    const float* ad1    = (const float*)d_in[10];
    const float* b1     = (const float*)d_in[11];
    const float* Wf     = (const float*)d_in[12];
    const float* bf     = (const float*)d_in[13];
    float* out = (float*)d_out;

    __half *h, *x1;
    float* acc;
    cudaGetSymbolAddress((void**)&h,   g_h);
    cudaGetSymbolAddress((void**)&x1,  g_x1);
    cudaGetSymbolAddress((void**)&acc, g_acc);

    static cudaStream_t s2 = nullptr;
    static cudaEvent_t evFork = nullptr, evJoin = nullptr;
    if (s2 == nullptr) {
        cudaStreamCreateWithFlags(&s2, cudaStreamNonBlocking);
        cudaEventCreateWithFlags(&evFork, cudaEventDisableTiming);
        cudaEventCreateWithFlags(&evJoin, cudaEventDisableTiming);
    }

    const int mb = (NN + 127) / 128;
    const int gb = (NN + 7) / 8;
    const int hb = (NE / 4 + 255) / 256;   // hist: 4 edges/thread
    const int fb = (NE / 2 + 255) / 256;   // fill: 2 edges/thread

    // ---- fork: CSR build on s2 (5-kernel chain), concurrent with GEMM0 ----
    cudaEventRecord(evFork, 0);
    cudaStreamWaitEvent(s2, evFork, 0);

    zerodetect_k<<<(NN + 255) / 256, 256, 0, s2>>>((const int*)ei);
    hist_k<<<hb, 256, 0, s2>>>(ei);
    scan1_k<<<NB_SCAN, 256, 0, s2>>>();
    scan23_k<<<NB_SCAN, 256, 0, s2>>>();
    fill_k<<<fb, 256, 0, s2>>>(ei);
    cudaEventRecord(evJoin, s2);

    gemm16_k<true, false, false><<<dim3(HC / 64, mb), 256>>>(
        x, nullptr, nullptr, W0, nullptr, as0, ad0, h, NN, 128, HC);

    cudaStreamWaitEvent(0, evJoin, 0);

    gather_k<true><<<gb, 256>>>(h, x1, b0, gamma0, beta0);

    // ---- layer 1 (A = x1 fp16) ----
    gemm16_k<true, false, true><<<dim3(HC / 64, mb), 256>>>(
        x1, nullptr, nullptr, W1, nullptr, as1, ad1, h, NN, HC, HC);
    gather_k<false><<<gb, 256>>>(h, acc, nullptr, nullptr, nullptr);

    // ---- JK-max + final projection: out = max(x1, acc + b1) @ Wf + bf ----
    gemm16_k<false, true, true><<<dim3(1, mb), 256>>>(
        x1, acc, b1, Wf, bf, nullptr, nullptr, out, NN, HC, 64);
}

// round 16
// speedup vs baseline: 1.1676x; 1.0303x over previous
#include <cuda_runtime.h>
#include <cuda_fp16.h>
#include <math.h>

#define NN 50000
#define NE 800000
#define NET (NE + NN)       // edges + self loops = 850000
#define HC 256              // H*C
#define NH 4
#define CC 64
#define NB_SCAN 196         // ceil(NN/256)

// ---------------- scratch (static device globals; no allocs) ----------------
__device__ __align__(16) __half g_h[NN * HC];     // transformed features (fp16, per layer)
__device__ __align__(16) __half g_x1[NN * HC];    // layer-0 activated output (fp16)
__device__ __align__(16) __half g_acc[NN * HC];   // layer-1 aggregation output (fp16)
__device__ __align__(16) float g_asrc[NN * NH];
__device__ __align__(16) float g_adst[NN * NH];
__device__ int g_deg[NN];
__device__ int g_off[NN + 1];
__device__ int g_cur[NN];
__device__ int g_part[NB_SCAN];
__device__ int g_adj[NET];                        // src ids grouped by dst
__device__ int g_is64;

// ---------------- zero deg (=1: self-loop pre-counted) + detect dtype ----------------
__global__ void zerodetect_k(const int* ei32) {
    int i = blockIdx.x * blockDim.x + threadIdx.x;
    if (i < NN) g_deg[i] = 1;
    if (i == 0) {
        int ok = 1;
        #pragma unroll
        for (int k = 0; k < 64; k++)
            if (ei32[2 * k + 1] != 0) ok = 0;
        g_is64 = ok;
    }
}

// ---------------- CSR build (real edges only; self-loops planted by scan23) ----------------
__global__ void hist_k(const void* __restrict__ ei) {
    int q = blockIdx.x * blockDim.x + threadIdx.x;
    int e = q * 4;
    if (e >= NE) return;
    int d0, d1, d2, d3;
    if (g_is64) {
        const longlong2* p = (const longlong2*)((const long long*)ei + NE);
        longlong2 a = p[q * 2];
        longlong2 b = p[q * 2 + 1];
        d0 = (int)a.x; d1 = (int)a.y; d2 = (int)b.x; d3 = (int)b.y;
    } else {
        int4 a = ((const int4*)((const int*)ei + NE))[q];
        d0 = a.x; d1 = a.y; d2 = a.z; d3 = a.w;
    }
    atomicAdd(&g_deg[d0], 1);
    atomicAdd(&g_deg[d1], 1);
    atomicAdd(&g_deg[d2], 1);
    atomicAdd(&g_deg[d3], 1);
}

__global__ void scan1_k() {
    __shared__ int sh[256];
    int i = blockIdx.x * 256 + threadIdx.x;
    int v = (i < NN) ? g_deg[i] : 0;
    sh[threadIdx.x] = v; __syncthreads();
    for (int o = 128; o; o >>= 1) {
        if (threadIdx.x < o) sh[threadIdx.x] += sh[threadIdx.x + o];
        __syncthreads();
    }
    if (threadIdx.x == 0) g_part[blockIdx.x] = sh[0];
}

// merged scan2+scan3: each block reduces its own prefix of g_part, then does
// the per-block exclusive scan, writes off/cur and plants the self-loop.
__global__ void scan23_k() {
    __shared__ int sh[256];
    __shared__ int base;
    const int t = threadIdx.x;

    int v = (t < blockIdx.x && t < NB_SCAN) ? g_part[t] : 0;
    sh[t] = v; __syncthreads();
    for (int o = 128; o; o >>= 1) {
        if (t < o) sh[t] += sh[t + o];
        __syncthreads();
    }
    if (t == 0) base = sh[0];
    __syncthreads();

    int i = blockIdx.x * 256 + t;
    int d = (i < NN) ? g_deg[i] : 0;
    sh[t] = d; __syncthreads();
    for (int o = 1; o < 256; o <<= 1) {
        int x = (t >= o) ? sh[t - o] : 0;
        __syncthreads();
        sh[t] += x;
        __syncthreads();
    }
    if (i < NN) {
        int off = base + sh[t] - d;
        g_off[i] = off;
        g_adj[off] = i;          // plant self-loop in first slot
        g_cur[i] = off + 1;      // real edges fill after it
        if (i == NN - 1) g_off[NN] = off + d;
    }
}

__global__ void fill_k(const void* __restrict__ ei) {
    int q = blockIdx.x * blockDim.x + threadIdx.x;
    int e = q * 2;
    if (e >= NE) return;
    int s0, s1, d0, d1;
    if (g_is64) {
        const long long* p = (const long long*)ei;
        longlong2 sv = ((const longlong2*)p)[q];
        longlong2 dv = ((const longlong2*)(p + NE))[q];
        s0 = (int)sv.x; s1 = (int)sv.y;
        d0 = (int)dv.x; d1 = (int)dv.y;
    } else {
        const int* p = (const int*)ei;
        int2 sv = ((const int2*)p)[q];
        int2 dv = ((const int2*)(p + NE))[q];
        s0 = sv.x; s1 = sv.y;
        d0 = dv.x; d1 = dv.y;
    }
    int p0 = atomicAdd(&g_cur[d0], 1);
    g_adj[p0] = s0;
    int p1 = atomicAdd(&g_cur[d1], 1);
    g_adj[p1] = s1;
}

// ---------------- tensor-core GEMM (fp16 HMMA, fp32 accum) ----------------
// ALPHA: fp16 output + per-row alpha dots (head = blockIdx.x).
// FMAX:  A-element = max(A, A2 + ab), A2 fp16; fp32 output with +bias.
// AHALF: A operand is fp16 in global memory.
#define APAD 40
#define BPAD 72
__device__ __forceinline__ unsigned su32(const void* p) {
    return (unsigned)__cvta_generic_to_shared(p);
}
__device__ __forceinline__ void ldm_x4(unsigned addr, unsigned& r0, unsigned& r1,
                                       unsigned& r2, unsigned& r3) {
    asm volatile("ldmatrix.sync.aligned.m8n8.x4.shared.b16 {%0,%1,%2,%3},[%4];"
                 : "=r"(r0), "=r"(r1), "=r"(r2), "=r"(r3) : "r"(addr));
}
__device__ __forceinline__ void ldm_x4t(unsigned addr, unsigned& r0, unsigned& r1,
                                        unsigned& r2, unsigned& r3) {
    asm volatile("ldmatrix.sync.aligned.m8n8.x4.trans.shared.b16 {%0,%1,%2,%3},[%4];"
                 : "=r"(r0), "=r"(r1), "=r"(r2), "=r"(r3) : "r"(addr));
}
__device__ __forceinline__ void mma16816(float& d0, float& d1, float& d2, float& d3,
                                         unsigned a0, unsigned a1, unsigned a2, unsigned a3,
                                         unsigned b0, unsigned b1) {
    asm volatile(
        "mma.sync.aligned.m16n8k16.row.col.f32.f16.f16.f32 "
        "{%0,%1,%2,%3},{%4,%5,%6,%7},{%8,%9},{%0,%1,%2,%3};"
        : "+f"(d0), "+f"(d1), "+f"(d2), "+f"(d3)
        : "r"(a0), "r"(a1), "r"(a2), "r"(a3), "r"(b0), "r"(b1));
}

template <bool ALPHA, bool FMAX, bool AHALF>
__global__ __launch_bounds__(256) void gemm16_k(
    const void* __restrict__ Av, const void* __restrict__ A2v,
    const float* __restrict__ ab, const float* __restrict__ B,
    const float* __restrict__ bias,
    const float* __restrict__ aS, const float* __restrict__ aD,
    void* __restrict__ Cv, int M, int K, int Nc)
{
    __shared__ __half As[128][APAD];
    __shared__ __half Bs[32][BPAD];
    __shared__ float sPs[128];
    __shared__ float sPd[128];

    const int tid = threadIdx.x;
    const int lane = tid & 31;
    const int warp = tid >> 5;
    const int wm = warp & 3;
    const int wn = warp >> 2;
    const int m0 = blockIdx.y * 128;
    const int n0 = blockIdx.x * 64;

    float acc[2][4][4];
    #pragma unroll
    for (int mt = 0; mt < 2; mt++)
        #pragma unroll
        for (int nt = 0; nt < 4; nt++)
            #pragma unroll
            for (int r = 0; r < 4; r++) acc[mt][nt][r] = 0.f;

    if (ALPHA && tid < 128) { sPs[tid] = 0.f; sPd[tid] = 0.f; }

    float4 ra[4], ran[4];
    uint4 ra16[2], ran16[2];
    float4 rb[2], rbn[2];

    auto load_fragA = [&](int kt, float4 (&la)[4], uint4 (&la16)[2]) {
        if (AHALF) {
            const __half* Ah = (const __half*)Av;
            #pragma unroll
            for (int i = 0; i < 2; i++) {
                int q = tid + i * 256;
                int row = q >> 2;
                int ks = (q & 3) * 8;
                uint4 v = make_uint4(0, 0, 0, 0);
                if (m0 + row < M) {
                    v = *(const uint4*)(Ah + (size_t)(m0 + row) * K + kt + ks);
                    if (FMAX) {
                        const __half* a2p = (const __half*)A2v + (size_t)(m0 + row) * K + kt + ks;
                        uint4 v2 = *(const uint4*)a2p;
                        float4 b20 = *(const float4*)(ab + kt + ks);
                        float4 b21 = *(const float4*)(ab + kt + ks + 4);
                        float2 x0 = __half22float2(*(__half2*)&v.x);
                        float2 x1 = __half22float2(*(__half2*)&v.y);
                        float2 x2 = __half22float2(*(__half2*)&v.z);
                        float2 x3 = __half22float2(*(__half2*)&v.w);
                        float2 y0 = __half22float2(*(__half2*)&v2.x);
                        float2 y1 = __half22float2(*(__half2*)&v2.y);
                        float2 y2 = __half22float2(*(__half2*)&v2.z);
                        float2 y3 = __half22float2(*(__half2*)&v2.w);
                        __half2 h0 = __floats2half2_rn(fmaxf(x0.x, y0.x + b20.x),
                                                       fmaxf(x0.y, y0.y + b20.y));
                        __half2 h1 = __floats2half2_rn(fmaxf(x1.x, y1.x + b20.z),
                                                       fmaxf(x1.y, y1.y + b20.w));
                        __half2 h2 = __floats2half2_rn(fmaxf(x2.x, y2.x + b21.x),
                                                       fmaxf(x2.y, y2.y + b21.y));
                        __half2 h3 = __floats2half2_rn(fmaxf(x3.x, y3.x + b21.z),
                                                       fmaxf(x3.y, y3.y + b21.w));
                        v.x = *(unsigned*)&h0;
                        v.y = *(unsigned*)&h1;
                        v.z = *(unsigned*)&h2;
                        v.w = *(unsigned*)&h3;
                    }
                }
                la16[i] = v;
            }
        } else {
            const float* A = (const float*)Av;
            #pragma unroll
            for (int i = 0; i < 4; i++) {
                int q = tid + i * 256;
                int row = q >> 3;
                int ks = (q & 7) * 4;
                float4 v = make_float4(0.f, 0.f, 0.f, 0.f);
                if (m0 + row < M)
                    v = *(const float4*)(A + (size_t)(m0 + row) * K + kt + ks);
                la[i] = v;
            }
        }
    };
    auto load_fragB = [&](int kt, float4 (&lb)[2]) {
        #pragma unroll
        for (int i = 0; i < 2; i++) {
            int q = tid + i * 256;
            int kr = q >> 4;
            int ns = (q & 15) * 4;
            lb[i] = *(const float4*)(B + (size_t)(kt + kr) * Nc + n0 + ns);
        }
    };
    auto store_frag = [&](const float4 (&la)[4], const uint4 (&la16)[2],
                          const float4 (&lb)[2]) {
        if (AHALF) {
            #pragma unroll
            for (int i = 0; i < 2; i++) {
                int q = tid + i * 256;
                int row = q >> 2;
                int ks = (q & 3) * 8;
                *(uint4*)&As[row][ks] = la16[i];
            }
        } else {
            #pragma unroll
            for (int i = 0; i < 4; i++) {
                int q = tid + i * 256;
                int row = q >> 3;
                int ks = (q & 7) * 4;
                *(__half2*)&As[row][ks]     = __floats2half2_rn(la[i].x, la[i].y);
                *(__half2*)&As[row][ks + 2] = __floats2half2_rn(la[i].z, la[i].w);
            }
        }
        #pragma unroll
        for (int i = 0; i < 2; i++) {
            int q = tid + i * 256;
            int kr = q >> 4;
            int ns = (q & 15) * 4;
            *(__half2*)&Bs[kr][ns]     = __floats2half2_rn(lb[i].x, lb[i].y);
            *(__half2*)&Bs[kr][ns + 2] = __floats2half2_rn(lb[i].z, lb[i].w);
        }
    };

    load_fragA(0, ra, ra16);
    load_fragB(0, rb);

    for (int kt = 0; kt < K; kt += 32) {
        store_frag(ra, ra16, rb);
        __syncthreads();

        if (kt + 32 < K) {
            load_fragA(kt + 32, ran, ran16);
            load_fragB(kt + 32, rbn);
        }

        #pragma unroll
        for (int kg = 0; kg < 2; kg++) {
            unsigned a[2][4], bq[2][4];
            #pragma unroll
            for (int mt = 0; mt < 2; mt++) {
                unsigned ad = su32(&As[wm * 32 + mt * 16 + (lane & 15)]
                                      [kg * 16 + (lane >> 4) * 8]);
                ldm_x4(ad, a[mt][0], a[mt][1], a[mt][2], a[mt][3]);
            }
            #pragma unroll
            for (int np = 0; np < 2; np++) {
                unsigned bd = su32(&Bs[kg * 16 + (lane & 15)]
                                      [wn * 32 + np * 16 + (lane >> 4) * 8]);
                ldm_x4t(bd, bq[np][0], bq[np][1], bq[np][2], bq[np][3]);
            }
            #pragma unroll
            for (int mt = 0; mt < 2; mt++)
                #pragma unroll
                for (int nt = 0; nt < 4; nt++) {
                    unsigned b0 = bq[nt >> 1][(nt & 1) * 2];
                    unsigned b1 = bq[nt >> 1][(nt & 1) * 2 + 1];
                    mma16816(acc[mt][nt][0], acc[mt][nt][1],
                             acc[mt][nt][2], acc[mt][nt][3],
                             a[mt][0], a[mt][1], a[mt][2], a[mt][3], b0, b1);
                }
        }
        __syncthreads();

        #pragma unroll
        for (int i = 0; i < 4; i++) ra[i] = ran[i];
        #pragma unroll
        for (int i = 0; i < 2; i++) { ra16[i] = ran16[i]; rb[i] = rbn[i]; }
    }

    #pragma unroll
    for (int mt = 0; mt < 2; mt++) {
        int row0 = m0 + wm * 32 + mt * 16 + (lane >> 2);
        #pragma unroll
        for (int nt = 0; nt < 4; nt++) {
            int col = n0 + wn * 32 + nt * 8 + 2 * (lane & 3);
            if (ALPHA) {
                __half* C = (__half*)Cv;
                if (row0 < M)
                    *(__half2*)(C + (size_t)row0 * Nc + col) =
                        __floats2half2_rn(acc[mt][nt][0], acc[mt][nt][1]);
                if (row0 + 8 < M)
                    *(__half2*)(C + (size_t)(row0 + 8) * Nc + col) =
                        __floats2half2_rn(acc[mt][nt][2], acc[mt][nt][3]);
            } else {
                float* C = (float*)Cv;
                float2 bv = *(const float2*)(bias + col);
                if (row0 < M) {
                    float2 v = make_float2(acc[mt][nt][0] + bv.x, acc[mt][nt][1] + bv.y);
                    *(float2*)(C + (size_t)row0 * Nc + col) = v;
                }
                if (row0 + 8 < M) {
                    float2 v = make_float2(acc[mt][nt][2] + bv.x, acc[mt][nt][3] + bv.y);
                    *(float2*)(C + (size_t)(row0 + 8) * Nc + col) = v;
                }
            }
        }
    }

    if (ALPHA) {
        #pragma unroll
        for (int mt = 0; mt < 2; mt++) {
            float psg = 0.f, psg8 = 0.f, pdg = 0.f, pdg8 = 0.f;
            #pragma unroll
            for (int nt = 0; nt < 4; nt++) {
                int col = n0 + wn * 32 + nt * 8 + 2 * (lane & 3);
                float2 sv = *(const float2*)(aS + col);
                float2 dv = *(const float2*)(aD + col);
                psg  += acc[mt][nt][0] * sv.x + acc[mt][nt][1] * sv.y;
                psg8 += acc[mt][nt][2] * sv.x + acc[mt][nt][3] * sv.y;
                pdg  += acc[mt][nt][0] * dv.x + acc[mt][nt][1] * dv.y;
                pdg8 += acc[mt][nt][2] * dv.x + acc[mt][nt][3] * dv.y;
            }
            #pragma unroll
            for (int o = 1; o <= 2; o <<= 1) {
                psg  += __shfl_xor_sync(0xffffffffu, psg, o);
                psg8 += __shfl_xor_sync(0xffffffffu, psg8, o);
                pdg  += __shfl_xor_sync(0xffffffffu, pdg, o);
                pdg8 += __shfl_xor_sync(0xffffffffu, pdg8, o);
            }
            if ((lane & 3) == 0) {
                int rl = wm * 32 + mt * 16 + (lane >> 2);
                atomicAdd(&sPs[rl], psg);
                atomicAdd(&sPs[rl + 8], psg8);
                atomicAdd(&sPd[rl], pdg);
                atomicAdd(&sPd[rl + 8], pdg8);
            }
        }
        __syncthreads();
        if (tid < 128) {
            int row = m0 + tid;
            if (row < M) {
                int head = blockIdx.x;
                g_asrc[row * 4 + head] = sPs[tid];
                g_adst[row * 4 + head] = sPd[tid];
            }
        }
    }
}

// ---------------- fused edge-softmax + CSR gather (fp16 features, fp16 out) ----------------
// 32 threads per node, 8 nodes per block, 4x unrolled, __ldcg.
// ACT=true: bias + BN(eval) + ELU epilogue. Output always fp16.
template <bool ACT>
__global__ __launch_bounds__(256) void gather_k(
    const __half* __restrict__ h, __half* __restrict__ outh,
    const float* __restrict__ b0,
    const float* __restrict__ gamma,
    const float* __restrict__ beta)
{
    int node = blockIdx.x * 8 + (threadIdx.x >> 5);
    if (node >= NN) return;
    int t = threadIdx.x & 31;
    int head = t >> 3;
    int oct = t & 7;
    int p = g_off[node];
    const int end = g_off[node + 1];

    const float ad = g_adst[node * 4 + head];
    float a[8];
    #pragma unroll
    for (int i = 0; i < 8; i++) a[i] = 0.f;
    float wsum = 0.f;

    const int coff = head * 64 + oct * 8;

    for (; p + 4 <= end; p += 4) {
        int s0 = g_adj[p + 0];
        int s1 = g_adj[p + 1];
        int s2 = g_adj[p + 2];
        int s3 = g_adj[p + 3];
        float e0 = g_asrc[s0 * 4 + head] + ad;
        float e1 = g_asrc[s1 * 4 + head] + ad;
        float e2 = g_asrc[s2 * 4 + head] + ad;
        float e3 = g_asrc[s3 * 4 + head] + ad;
        uint4 r0 = __ldcg((const uint4*)(h + (size_t)s0 * HC + coff));
        uint4 r1 = __ldcg((const uint4*)(h + (size_t)s1 * HC + coff));
        uint4 r2 = __ldcg((const uint4*)(h + (size_t)s2 * HC + coff));
        uint4 r3 = __ldcg((const uint4*)(h + (size_t)s3 * HC + coff));
        e0 = e0 > 0.f ? e0 : 0.2f * e0;
        e1 = e1 > 0.f ? e1 : 0.2f * e1;
        e2 = e2 > 0.f ? e2 : 0.2f * e2;
        e3 = e3 > 0.f ? e3 : 0.2f * e3;
        float w0 = __expf(e0), w1 = __expf(e1), w2 = __expf(e2), w3 = __expf(e3);
        wsum += (w0 + w1) + (w2 + w3);
        const uint4* rr[4] = {&r0, &r1, &r2, &r3};
        float ww[4] = {w0, w1, w2, w3};
        #pragma unroll
        for (int u = 0; u < 4; u++) {
            float2 f0 = __half22float2(*(const __half2*)&rr[u]->x);
            float2 f1 = __half22float2(*(const __half2*)&rr[u]->y);
            float2 f2 = __half22float2(*(const __half2*)&rr[u]->z);
            float2 f3 = __half22float2(*(const __half2*)&rr[u]->w);
            float w = ww[u];
            a[0] = fmaf(w, f0.x, a[0]);
            a[1] = fmaf(w, f0.y, a[1]);
            a[2] = fmaf(w, f1.x, a[2]);
            a[3] = fmaf(w, f1.y, a[3]);
            a[4] = fmaf(w, f2.x, a[4]);
            a[5] = fmaf(w, f2.y, a[5]);
            a[6] = fmaf(w, f3.x, a[6]);
            a[7] = fmaf(w, f3.y, a[7]);
        }
    }
    for (; p < end; p++) {
        int s = g_adj[p];
        float e = g_asrc[s * 4 + head] + ad;
        e = e > 0.f ? e : 0.2f * e;
        float w = __expf(e);
        uint4 raw = __ldcg((const uint4*)(h + (size_t)s * HC + coff));
        float2 f0 = __half22float2(*(__half2*)&raw.x);
        float2 f1 = __half22float2(*(__half2*)&raw.y);
        float2 f2 = __half22float2(*(__half2*)&raw.z);
        float2 f3 = __half22float2(*(__half2*)&raw.w);
        a[0] = fmaf(w, f0.x, a[0]);
        a[1] = fmaf(w, f0.y, a[1]);
        a[2] = fmaf(w, f1.x, a[2]);
        a[3] = fmaf(w, f1.y, a[3]);
        a[4] = fmaf(w, f2.x, a[4]);
        a[5] = fmaf(w, f2.y, a[5]);
        a[6] = fmaf(w, f3.x, a[6]);
        a[7] = fmaf(w, f3.y, a[7]);
        wsum += w;
    }

    float inv = 1.0f / (wsum + 1e-16f);
    #pragma unroll
    for (int i = 0; i < 8; i++) a[i] *= inv;

    if (ACT) {
        const float r = rsqrtf(1.0f + 1e-5f);
        #pragma unroll
        for (int u = 0; u < 2; u++) {
            float4 bb = *(const float4*)(b0 + coff + u * 4);
            float4 gg = *(const float4*)(gamma + coff + u * 4);
            float4 be = *(const float4*)(beta + coff + u * 4);
            float v0 = (a[u * 4 + 0] + bb.x) * (gg.x * r) + be.x;
            float v1 = (a[u * 4 + 1] + bb.y) * (gg.y * r) + be.y;
            float v2 = (a[u * 4 + 2] + bb.z) * (gg.z * r) + be.z;
            float v3 = (a[u * 4 + 3] + bb.w) * (gg.w * r) + be.w;
            a[u * 4 + 0] = v0 > 0.f ? v0 : expm1f(v0);
            a[u * 4 + 1] = v1 > 0.f ? v1 : expm1f(v1);
            a[u * 4 + 2] = v2 > 0.f ? v2 : expm1f(v2);
            a[u * 4 + 3] = v3 > 0.f ? v3 : expm1f(v3);
        }
    }
    __half2 h0 = __floats2half2_rn(a[0], a[1]);
    __half2 h1 = __floats2half2_rn(a[2], a[3]);
    __half2 h2 = __floats2half2_rn(a[4], a[5]);
    __half2 h3 = __floats2half2_rn(a[6], a[7]);
    uint4 pk;
    pk.x = *(unsigned*)&h0;
    pk.y = *(unsigned*)&h1;
    pk.z = *(unsigned*)&h2;
    pk.w = *(unsigned*)&h3;
    *(uint4*)(outh + (size_t)node * HC + coff) = pk;
}

// ---------------- launch ----------------
extern "C" void kernel_launch(void* const* d_in, const int* in_sizes, int n_in,
                              void* d_out, int out_size)
{
    const float* x      = (const float*)d_in[0];
    const void*  ei     = d_in[1];
    const float* W0     = (const float*)d_in[2];
    const float* as0    = (const float*)d_in[3];
    const float* ad0    = (const float*)d_in[4];
    const float* b0     = (const float*)d_in[5];
    const float* gamma0 = (const float*)d_in[6];
    const float* beta0  = (const float*)d_in[7];
    const float* W1     = (const float*)d_in[8];
    const float* as1    = (const float*)d_in[9];
    const float* ad1    = (const float*)d_in[10];
    const float* b1     = (const float*)d_in[11];
    const float* Wf     = (const float*)d_in[12];
    const float* bf     = (const float*)d_in[13];
    float* out = (float*)d_out;

    __half *h, *x1, *acc;
    cudaGetSymbolAddress((void**)&h,   g_h);
    cudaGetSymbolAddress((void**)&x1,  g_x1);
    cudaGetSymbolAddress((void**)&acc, g_acc);

    static cudaStream_t s2 = nullptr;
    static cudaEvent_t evFork = nullptr, evJoin = nullptr;
    if (s2 == nullptr) {
        cudaStreamCreateWithFlags(&s2, cudaStreamNonBlocking);
        cudaEventCreateWithFlags(&evFork, cudaEventDisableTiming);
        cudaEventCreateWithFlags(&evJoin, cudaEventDisableTiming);
    }

    const int mb = (NN + 127) / 128;
    const int gb = (NN + 7) / 8;
    const int hb = (NE / 4 + 255) / 256;   // hist: 4 edges/thread
    const int fb = (NE / 2 + 255) / 256;   // fill: 2 edges/thread

    // ---- fork: CSR build on s2 (5-kernel chain), concurrent with GEMM0 ----
    cudaEventRecord(evFork, 0);
    cudaStreamWaitEvent(s2, evFork, 0);

    zerodetect_k<<<(NN + 255) / 256, 256, 0, s2>>>((const int*)ei);
    hist_k<<<hb, 256, 0, s2>>>(ei);
    scan1_k<<<NB_SCAN, 256, 0, s2>>>();
    scan23_k<<<NB_SCAN, 256, 0, s2>>>();
    fill_k<<<fb, 256, 0, s2>>>(ei);
    cudaEventRecord(evJoin, s2);

    gemm16_k<true, false, false><<<dim3(HC / 64, mb), 256>>>(
        x, nullptr, nullptr, W0, nullptr, as0, ad0, h, NN, 128, HC);

    cudaStreamWaitEvent(0, evJoin, 0);

    gather_k<true><<<gb, 256>>>(h, x1, b0, gamma0, beta0);

    // ---- layer 1 (A = x1 fp16) ----
    gemm16_k<true, false, true><<<dim3(HC / 64, mb), 256>>>(
        x1, nullptr, nullptr, W1, nullptr, as1, ad1, h, NN, HC, HC);
    gather_k<false><<<gb, 256>>>(h, acc, nullptr, nullptr, nullptr);

    // ---- JK-max + final projection: out = max(x1, acc + b1) @ Wf + bf ----
    gemm16_k<false, true, true><<<dim3(1, mb), 256>>>(
        x1, acc, b1, Wf, bf, nullptr, nullptr, out, NN, HC, 64);
}